// round 15
// baseline (speedup 1.0000x reference)
#include <cuda_runtime.h>

// Perona-Malik diffusion, 3 iterations fused in ONE kernel.
// Warp-register temporal pipeline (6 stages), 4 cols/lane via float4,
// horizontal via shuffles, vertical via register sliding window.
// Frozen (R12 config, best = 88.4us): CHUNK=74, 14 bands, 2240 warp-strips
// in 560 x 128-thread blocks (one wave at 4 blocks/SM), 128-reg cap,
// grouped reciprocal, 2-shuffle divergence, unroll-4 interior, 2-ahead
// prefetch, fully unrolled warm-up.
// (R13's CHUNK=80 lengthened the per-warp critical path 7% - reverted.)
// R14: guard specialization split into independent X/Y axes. Y-only
// boundary warps (strips 1-8, bands 0/13) use warp-uniform y-branches
// instead of per-lane selects; X-only warps skip y checks entirely.

#define NB 16
#define H  1024
#define W  1024

#define HALO   8
#define OUTWC  112
#define NSTRIP 10
#define CHUNK  74
#define NBANDS 14     // 14*74 = 1036 >= 1024 (last band stores 62 rows)

#define K2_64  0.16f            // 64 * kappa^2
#define K2E    0.16000064f      // 64 * (kappa^2 + eps)
#define DTC    0.00390625f      // DT / 64

__device__ __forceinline__ float4 mk4(float v) { return make_float4(v, v, v, v); }

struct Flux { float4 fx, fy; };

// flux (scaled by 8) at one row from input rows vm, vc, vp.
__device__ __forceinline__ Flux fluxrow(const float4 vm, const float4 vc,
                                        const float4 vp, const bool valid)
{
    const unsigned m = 0xffffffffu;
    const float a0 = vm.x + 2.f*vc.x + vp.x;
    const float a1 = vm.y + 2.f*vc.y + vp.y;
    const float a2 = vm.z + 2.f*vc.z + vp.z;
    const float a3 = vm.w + 2.f*vc.w + vp.w;
    const float b0 = vp.x - vm.x;
    const float b1 = vp.y - vm.y;
    const float b2 = vp.z - vm.z;
    const float b3 = vp.w - vm.w;
    const float aL = __shfl_up_sync(m, a3, 1);
    const float aR = __shfl_down_sync(m, a0, 1);
    const float bL = __shfl_up_sync(m, b3, 1);
    const float bR = __shfl_down_sync(m, b0, 1);
    const float gx0 = a1 - aL;                 // 8*gx
    const float gx1 = a2 - a0;
    const float gx2 = a3 - a1;
    const float gx3 = aR - a2;
    const float gy0 = bL + 2.f*b0 + b1;        // 8*gy
    const float gy1 = b0 + 2.f*b1 + b2;
    const float gy2 = b1 + 2.f*b2 + b3;
    const float gy3 = b2 + 2.f*b3 + bR;
    const float d0 = fmaf(gx0, gx0, fmaf(gy0, gy0, K2E));
    const float d1 = fmaf(gx1, gx1, fmaf(gy1, gy1, K2E));
    const float d2 = fmaf(gx2, gx2, fmaf(gy2, gy2, K2E));
    const float d3 = fmaf(gx3, gx3, fmaf(gy3, gy3, K2E));

    // grouped reciprocal: one RCP for four conduction coefficients.
    const float d01  = d0 * d1;
    const float d23  = d2 * d3;
    const float invK = __fdividef(K2_64, d01 * d23);
    float c0 = (d1 * d23) * invK;
    float c1 = (d0 * d23) * invK;
    float c2 = (d01 * d3) * invK;
    float c3 = (d01 * d2) * invK;
    c0 = valid ? c0 : 0.f;
    c1 = valid ? c1 : 0.f;
    c2 = valid ? c2 : 0.f;
    c3 = valid ? c3 : 0.f;

    Flux f;
    f.fx = make_float4(c0*gx0, c1*gx1, c2*gx2, c3*gx3);   // 8*flux
    f.fy = make_float4(c0*gy0, c1*gy1, c2*gy2, c3*gy3);
    return f;
}

// out = base + (DT/64) * dsum8; u/v identity -> only 2 shuffles.
__device__ __forceinline__ float4 updrow(const float4 base,
                                         const Flux f0, const Flux f1,
                                         const Flux f2, const bool valid)
{
    const unsigned m = 0xffffffffu;
    const float p0 = f0.fx.x + 2.f*f1.fx.x + f2.fx.x;
    const float p1 = f0.fx.y + 2.f*f1.fx.y + f2.fx.y;
    const float p2 = f0.fx.z + 2.f*f1.fx.z + f2.fx.z;
    const float p3 = f0.fx.w + 2.f*f1.fx.w + f2.fx.w;
    const float q0 = f2.fy.x - f0.fy.x;
    const float q1 = f2.fy.y - f0.fy.y;
    const float q2 = f2.fy.z - f0.fy.z;
    const float q3 = f2.fy.w - f0.fy.w;

    const float u0 = p0 + q0, u1 = p1 + q1, u2 = p2 + q2, u3 = p3 + q3;
    const float v0 = q0 - p0, v1 = q1 - p1, v2 = q2 - p2, v3 = q3 - p3;

    const float vL = __shfl_up_sync(m, v3, 1);
    const float uR = __shfl_down_sync(m, u0, 1);

    const float d0 = fmaf(2.f, q0, vL) + u1;
    const float d1 = fmaf(2.f, q1, v0) + u2;
    const float d2 = fmaf(2.f, q2, v1) + u3;
    const float d3 = fmaf(2.f, q3, v2) + uR;

    float4 o;
    o.x = valid ? fmaf(DTC, d0, base.x) : 0.f;
    o.y = valid ? fmaf(DTC, d1, base.y) : 0.f;
    o.z = valid ? fmaf(DTC, d2, base.z) : 0.f;
    o.w = valid ? fmaf(DTC, d3, base.w) : 0.f;
    return o;
}

// XG: per-lane column guard needed (strips 0 / NSTRIP-1).
// YG: row-range guard needed (band 0 / last band) - warp-uniform checks.
template<bool XG, bool YG>
__device__ __forceinline__ void run_strip(const float* __restrict__ img,
                                          float* __restrict__ op,
                                          const int x0, const int y0,
                                          const int nrows,
                                          const bool colv, const bool st_ok)
{
    const float* lp = img + (size_t)(y0 - 6) * W + x0;   // next row to load
    float*       sp = op  + (size_t)y0 * W + x0;         // next row to store

    int ly = y0 - 6;
    auto load = [&]() -> float4 {
        float4 v;
        if (XG || YG) {
            const bool okx = XG ? colv : true;                       // per-lane
            const bool oky = YG ? ((unsigned)ly < (unsigned)H) : true; // uniform
            if (YG) ++ly;
            v = (okx && oky) ? __ldg(reinterpret_cast<const float4*>(lp))
                             : mk4(0.f);
        } else {
            v = __ldg(reinterpret_cast<const float4*>(lp));
        }
        lp += W;
        return v;
    };
    auto rv = [&](int y) -> bool {
        const bool okx = XG ? colv : true;
        const bool oky = YG ? ((unsigned)y < (unsigned)H) : true;
        return okx && oky;
    };

    // 2-ahead load prefetch: i0..i2 window + i3 in flight
    float4 i0 = load();
    float4 i1 = load();
    float4 i2 = load();
    float4 i3 = load();

    Flux zf; zf.fx = mk4(0.f); zf.fy = mk4(0.f);
    Flux  f1a = zf, f1b = zf, f2a = zf, f2b = zf, f3a = zf, f3b = zf;
    float4 o1a = mk4(0.f), o1b = o1a, o2a = o1a, o2b = o1a;

    auto step = [&](int y) -> float4 {
        const float4 inext = load();              // 2 rows ahead of use
        const Flux   f1c = fluxrow(i0, i1, i2,         rv(y + 5));
        const float4 o1c = updrow (i0, f1a, f1b, f1c,  rv(y + 4));
        const Flux   f2c = fluxrow(o1a, o1b, o1c,      rv(y + 3));
        const float4 o2c = updrow (o1a, f2a, f2b, f2c, rv(y + 2));
        const Flux   f3c = fluxrow(o2a, o2b, o2c,      rv(y + 1));
        const float4 o3  = updrow (o2a, f3a, f3b, f3c, rv(y));
        i0 = i1; i1 = i2; i2 = i3; i3 = inext;
        f1a = f1b; f1b = f1c;
        o1a = o1b; o1b = o1c;
        f2a = f2b; f2b = f2c;
        o2a = o2b; o2b = o2c;
        f3a = f3b; f3b = f3c;
        return o3;
    };

    // warm-up: 10 steps, nothing stored (fully unrolled)
    #pragma unroll
    for (int k = 0; k < 10; ++k)
        (void)step(y0 - 10 + k);

    if (XG || YG) {
        #pragma unroll 4
        for (int y = y0; y < y0 + nrows; ++y) {
            const float4 o3 = step(y);
            if (st_ok)
                *reinterpret_cast<float4*>(sp) = o3;
            sp += W;
        }
    } else {
        // interior: cross-step overlap via wide unroll
        #pragma unroll 4
        for (int y = y0; y < y0 + CHUNK; ++y) {
            const float4 o3 = step(y);
            if (st_ok)
                *reinterpret_cast<float4*>(sp) = o3;
            sp += W;
        }
    }
}

__global__ __launch_bounds__(128, 4)       // cap 128 regs -> 4 blocks/SM
void pm_fused3(const float* __restrict__ in, float* __restrict__ out)
{
    const int lane = threadIdx.x & 31;
    const int warp = threadIdx.x >> 5;

    // flattened work item: 10 strips x 14 bands x 16 images = 2240 warps
    const int item  = blockIdx.x * 4 + warp;
    const int image = item / (NSTRIP * NBANDS);
    const int rem   = item - image * (NSTRIP * NBANDS);
    const int strip = rem / NBANDS;
    const int band  = rem - strip * NBANDS;

    const int x0 = strip * OUTWC - HALO + lane * 4;
    const int y0 = band * CHUNK;
    const int nrows = (band == NBANDS - 1) ? (H - y0) : CHUNK;   // 62 or 74

    const size_t plane = (size_t)image * (size_t)(H * W);
    const float* __restrict__ img = in  + plane;
    float*       __restrict__ op  = out + plane;

    const bool colv  = (x0 >= 0) && (x0 + 4 <= W);
    const bool st_ok = colv && (lane >= HALO / 4) && (lane < 32 - HALO / 4);

    // guard requirements along each axis (loads span rows y0-6 .. y0+CHUNK+7)
    const bool xb = (strip == 0) || (strip == NSTRIP - 1);
    const bool yb = (band == 0) || (y0 + CHUNK + 7 >= H);

    if (!xb && !yb)      run_strip<false, false>(img, op, x0, y0, nrows, colv, st_ok);
    else if (xb && !yb)  run_strip<true,  false>(img, op, x0, y0, nrows, colv, st_ok);
    else if (!xb && yb)  run_strip<false, true >(img, op, x0, y0, nrows, colv, st_ok);
    else                 run_strip<true,  true >(img, op, x0, y0, nrows, colv, st_ok);
}

extern "C" void kernel_launch(void* const* d_in, const int* in_sizes, int n_in,
                              void* d_out, int out_size)
{
    const float* image = (const float*)d_in[0];
    float* out = (float*)d_out;

    // 2240 work items / 4 warps per block = 560 blocks: exactly one wave
    // at 4 blocks/SM residency (592 slots on 148 SMs).
    pm_fused3<<<560, 128>>>(image, out);
}

// round 16
// speedup vs baseline: 1.6669x; 1.6669x over previous
#include <cuda_runtime.h>

// Perona-Malik diffusion, 3 iterations fused in ONE kernel.
// Warp-register temporal pipeline (6 stages), 4 cols/lane via float4,
// horizontal via shuffles, vertical via register sliding window.
// R15 = exact revert to R12 (best, 88.4us): grouped reciprocal (1 RCP per
// flux row), 2-shuffle divergence, exactly-one-wave scheduling (2240
// warp-strips, 560 blocks, 128-reg cap), unroll-4 interior, 2-row load
// prefetch, fully unrolled warm-up, TWO template instantiations only
// (R14's four-way split overflowed the instruction cache; R13's CHUNK=80
// lengthened the per-warp critical path - both reverted).

#define NB 16
#define H  1024
#define W  1024

#define HALO   8
#define OUTWC  112
#define NSTRIP 10
#define CHUNK  74
#define NBANDS 14     // 14*74 = 1036 >= 1024 (last band stores 62 rows)

#define K2_64  0.16f            // 64 * kappa^2
#define K2E    0.16000064f      // 64 * (kappa^2 + eps)
#define DTC    0.00390625f      // DT / 64

__device__ __forceinline__ float4 mk4(float v) { return make_float4(v, v, v, v); }

struct Flux { float4 fx, fy; };

// flux (scaled by 8) at one row from input rows vm, vc, vp.
__device__ __forceinline__ Flux fluxrow(const float4 vm, const float4 vc,
                                        const float4 vp, const bool valid)
{
    const unsigned m = 0xffffffffu;
    const float a0 = vm.x + 2.f*vc.x + vp.x;
    const float a1 = vm.y + 2.f*vc.y + vp.y;
    const float a2 = vm.z + 2.f*vc.z + vp.z;
    const float a3 = vm.w + 2.f*vc.w + vp.w;
    const float b0 = vp.x - vm.x;
    const float b1 = vp.y - vm.y;
    const float b2 = vp.z - vm.z;
    const float b3 = vp.w - vm.w;
    const float aL = __shfl_up_sync(m, a3, 1);
    const float aR = __shfl_down_sync(m, a0, 1);
    const float bL = __shfl_up_sync(m, b3, 1);
    const float bR = __shfl_down_sync(m, b0, 1);
    const float gx0 = a1 - aL;                 // 8*gx
    const float gx1 = a2 - a0;
    const float gx2 = a3 - a1;
    const float gx3 = aR - a2;
    const float gy0 = bL + 2.f*b0 + b1;        // 8*gy
    const float gy1 = b0 + 2.f*b1 + b2;
    const float gy2 = b1 + 2.f*b2 + b3;
    const float gy3 = b2 + 2.f*b3 + bR;
    const float d0 = fmaf(gx0, gx0, fmaf(gy0, gy0, K2E));
    const float d1 = fmaf(gx1, gx1, fmaf(gy1, gy1, K2E));
    const float d2 = fmaf(gx2, gx2, fmaf(gy2, gy2, K2E));
    const float d3 = fmaf(gx3, gx3, fmaf(gy3, gy3, K2E));

    // grouped reciprocal: one RCP for four conduction coefficients.
    const float d01  = d0 * d1;
    const float d23  = d2 * d3;
    const float invK = __fdividef(K2_64, d01 * d23);
    float c0 = (d1 * d23) * invK;
    float c1 = (d0 * d23) * invK;
    float c2 = (d01 * d3) * invK;
    float c3 = (d01 * d2) * invK;
    c0 = valid ? c0 : 0.f;
    c1 = valid ? c1 : 0.f;
    c2 = valid ? c2 : 0.f;
    c3 = valid ? c3 : 0.f;

    Flux f;
    f.fx = make_float4(c0*gx0, c1*gx1, c2*gx2, c3*gx3);   // 8*flux
    f.fy = make_float4(c0*gy0, c1*gy1, c2*gy2, c3*gy3);
    return f;
}

// out = base + (DT/64) * dsum8; u/v identity -> only 2 shuffles.
__device__ __forceinline__ float4 updrow(const float4 base,
                                         const Flux f0, const Flux f1,
                                         const Flux f2, const bool valid)
{
    const unsigned m = 0xffffffffu;
    const float p0 = f0.fx.x + 2.f*f1.fx.x + f2.fx.x;
    const float p1 = f0.fx.y + 2.f*f1.fx.y + f2.fx.y;
    const float p2 = f0.fx.z + 2.f*f1.fx.z + f2.fx.z;
    const float p3 = f0.fx.w + 2.f*f1.fx.w + f2.fx.w;
    const float q0 = f2.fy.x - f0.fy.x;
    const float q1 = f2.fy.y - f0.fy.y;
    const float q2 = f2.fy.z - f0.fy.z;
    const float q3 = f2.fy.w - f0.fy.w;

    const float u0 = p0 + q0, u1 = p1 + q1, u2 = p2 + q2, u3 = p3 + q3;
    const float v0 = q0 - p0, v1 = q1 - p1, v2 = q2 - p2, v3 = q3 - p3;

    const float vL = __shfl_up_sync(m, v3, 1);
    const float uR = __shfl_down_sync(m, u0, 1);

    const float d0 = fmaf(2.f, q0, vL) + u1;
    const float d1 = fmaf(2.f, q1, v0) + u2;
    const float d2 = fmaf(2.f, q2, v1) + u3;
    const float d3 = fmaf(2.f, q3, v2) + uR;

    float4 o;
    o.x = valid ? fmaf(DTC, d0, base.x) : 0.f;
    o.y = valid ? fmaf(DTC, d1, base.y) : 0.f;
    o.z = valid ? fmaf(DTC, d2, base.z) : 0.f;
    o.w = valid ? fmaf(DTC, d3, base.w) : 0.f;
    return o;
}

// GUARD=true: boundary warps, full predication, variable rows.
// GUARD=false: fully interior warps, no checks, compile-time row count.
template<bool GUARD>
__device__ __forceinline__ void run_strip(const float* __restrict__ img,
                                          float* __restrict__ op,
                                          const int x0, const int y0,
                                          const int nrows,
                                          const bool colv, const bool st_ok)
{
    const float* lp = img + (size_t)(y0 - 6) * W + x0;   // next row to load
    float*       sp = op  + (size_t)y0 * W + x0;         // next row to store

    int ly = y0 - 6;
    auto load = [&]() -> float4 {
        float4 v;
        if (GUARD) {
            v = (colv && (unsigned)ly < (unsigned)H)
                    ? __ldg(reinterpret_cast<const float4*>(lp)) : mk4(0.f);
            ++ly;
        } else {
            v = __ldg(reinterpret_cast<const float4*>(lp));
        }
        lp += W;
        return v;
    };
    auto rv = [&](int y) -> bool {
        return GUARD ? (colv && (unsigned)y < (unsigned)H) : true;
    };

    // 2-ahead load prefetch: i0..i2 window + i3 in flight
    float4 i0 = load();
    float4 i1 = load();
    float4 i2 = load();
    float4 i3 = load();

    Flux zf; zf.fx = mk4(0.f); zf.fy = mk4(0.f);
    Flux  f1a = zf, f1b = zf, f2a = zf, f2b = zf, f3a = zf, f3b = zf;
    float4 o1a = mk4(0.f), o1b = o1a, o2a = o1a, o2b = o1a;

    auto step = [&](int y) -> float4 {
        const float4 inext = load();              // 2 rows ahead of use
        const Flux   f1c = fluxrow(i0, i1, i2,         rv(y + 5));
        const float4 o1c = updrow (i0, f1a, f1b, f1c,  rv(y + 4));
        const Flux   f2c = fluxrow(o1a, o1b, o1c,      rv(y + 3));
        const float4 o2c = updrow (o1a, f2a, f2b, f2c, rv(y + 2));
        const Flux   f3c = fluxrow(o2a, o2b, o2c,      rv(y + 1));
        const float4 o3  = updrow (o2a, f3a, f3b, f3c, rv(y));
        i0 = i1; i1 = i2; i2 = i3; i3 = inext;
        f1a = f1b; f1b = f1c;
        o1a = o1b; o1b = o1c;
        f2a = f2b; f2b = f2c;
        o2a = o2b; o2b = o2c;
        f3a = f3b; f3b = f3c;
        return o3;
    };

    // warm-up: 10 steps, nothing stored (fully unrolled)
    #pragma unroll
    for (int k = 0; k < 10; ++k)
        (void)step(y0 - 10 + k);

    if (GUARD) {
        #pragma unroll 2
        for (int y = y0; y < y0 + nrows; ++y) {
            const float4 o3 = step(y);
            if (st_ok)
                *reinterpret_cast<float4*>(sp) = o3;
            sp += W;
        }
    } else {
        // interior: wide unroll so ptxas can overlap stages across steps
        #pragma unroll 4
        for (int y = y0; y < y0 + CHUNK; ++y) {
            const float4 o3 = step(y);
            if (st_ok)
                *reinterpret_cast<float4*>(sp) = o3;
            sp += W;
        }
    }
}

__global__ __launch_bounds__(128, 4)       // cap 128 regs -> 4 blocks/SM
void pm_fused3(const float* __restrict__ in, float* __restrict__ out)
{
    const int lane = threadIdx.x & 31;
    const int warp = threadIdx.x >> 5;

    // flattened work item: 10 strips x 14 bands x 16 images = 2240 warps
    const int item  = blockIdx.x * 4 + warp;
    const int image = item / (NSTRIP * NBANDS);
    const int rem   = item - image * (NSTRIP * NBANDS);
    const int strip = rem / NBANDS;
    const int band  = rem - strip * NBANDS;

    const int x0 = strip * OUTWC - HALO + lane * 4;
    const int y0 = band * CHUNK;
    const int nrows = (band == NBANDS - 1) ? (H - y0) : CHUNK;   // 62 or 74

    const size_t plane = (size_t)image * (size_t)(H * W);
    const float* __restrict__ img = in  + plane;
    float*       __restrict__ op  = out + plane;

    const bool colv  = (x0 >= 0) && (x0 + 4 <= W);
    const bool st_ok = colv && (lane >= HALO / 4) && (lane < 32 - HALO / 4);

    const bool interior = (strip >= 1) && (strip <= NSTRIP - 2) &&
                          (band >= 1) && (y0 + CHUNK + 7 < H);

    if (interior)
        run_strip<false>(img, op, x0, y0, CHUNK, true, st_ok);
    else
        run_strip<true>(img, op, x0, y0, nrows, colv, st_ok);
}

extern "C" void kernel_launch(void* const* d_in, const int* in_sizes, int n_in,
                              void* d_out, int out_size)
{
    const float* image = (const float*)d_in[0];
    float* out = (float*)d_out;

    // 2240 work items / 4 warps per block = 560 blocks: exactly one wave
    // at 4 blocks/SM residency (592 slots on 148 SMs).
    pm_fused3<<<560, 128>>>(image, out);
}

// round 17
// speedup vs baseline: 1.7188x; 1.0311x over previous
#include <cuda_runtime.h>

// Perona-Malik diffusion, 3 iterations fused in ONE kernel.
// Warp-register temporal pipeline (6 stages), 4 cols/lane via float4,
// horizontal via shuffles, vertical via register sliding window.
// Frozen R12 config (best 88.4us): CHUNK=74, 2240 warp-strips, 560 blocks
// (one wave at 4 blocks/SM), 128-reg cap, grouped reciprocal, 2-shuffle
// divergence, unroll-4 interior, 2-ahead prefetch, TWO instantiations.
// R16: STAGED warm-up. During pipeline fill, stages beyond the fill front
// produced dead values (o1 needed from k>=2, f2 from k>=4, o2 from k>=6,
// f3 from k>=8, o3 never) - do_step<S> computes only live stages, saving
// ~4.8 full steps (~5.7% of each warp's critical path) and ~45% of the
// warm-up code footprint. Tail has no such waste (schedule is diagonal).

#define NB 16
#define H  1024
#define W  1024

#define HALO   8
#define OUTWC  112
#define NSTRIP 10
#define CHUNK  74
#define NBANDS 14     // 14*74 = 1036 >= 1024 (last band stores 62 rows)

#define K2_64  0.16f            // 64 * kappa^2
#define K2E    0.16000064f      // 64 * (kappa^2 + eps)
#define DTC    0.00390625f      // DT / 64

__device__ __forceinline__ float4 mk4(float v) { return make_float4(v, v, v, v); }

struct Flux { float4 fx, fy; };

// flux (scaled by 8) at one row from input rows vm, vc, vp.
__device__ __forceinline__ Flux fluxrow(const float4 vm, const float4 vc,
                                        const float4 vp, const bool valid)
{
    const unsigned m = 0xffffffffu;
    const float a0 = vm.x + 2.f*vc.x + vp.x;
    const float a1 = vm.y + 2.f*vc.y + vp.y;
    const float a2 = vm.z + 2.f*vc.z + vp.z;
    const float a3 = vm.w + 2.f*vc.w + vp.w;
    const float b0 = vp.x - vm.x;
    const float b1 = vp.y - vm.y;
    const float b2 = vp.z - vm.z;
    const float b3 = vp.w - vm.w;
    const float aL = __shfl_up_sync(m, a3, 1);
    const float aR = __shfl_down_sync(m, a0, 1);
    const float bL = __shfl_up_sync(m, b3, 1);
    const float bR = __shfl_down_sync(m, b0, 1);
    const float gx0 = a1 - aL;                 // 8*gx
    const float gx1 = a2 - a0;
    const float gx2 = a3 - a1;
    const float gx3 = aR - a2;
    const float gy0 = bL + 2.f*b0 + b1;        // 8*gy
    const float gy1 = b0 + 2.f*b1 + b2;
    const float gy2 = b1 + 2.f*b2 + b3;
    const float gy3 = b2 + 2.f*b3 + bR;
    const float d0 = fmaf(gx0, gx0, fmaf(gy0, gy0, K2E));
    const float d1 = fmaf(gx1, gx1, fmaf(gy1, gy1, K2E));
    const float d2 = fmaf(gx2, gx2, fmaf(gy2, gy2, K2E));
    const float d3 = fmaf(gx3, gx3, fmaf(gy3, gy3, K2E));

    // grouped reciprocal: one RCP for four conduction coefficients.
    const float d01  = d0 * d1;
    const float d23  = d2 * d3;
    const float invK = __fdividef(K2_64, d01 * d23);
    float c0 = (d1 * d23) * invK;
    float c1 = (d0 * d23) * invK;
    float c2 = (d01 * d3) * invK;
    float c3 = (d01 * d2) * invK;
    c0 = valid ? c0 : 0.f;
    c1 = valid ? c1 : 0.f;
    c2 = valid ? c2 : 0.f;
    c3 = valid ? c3 : 0.f;

    Flux f;
    f.fx = make_float4(c0*gx0, c1*gx1, c2*gx2, c3*gx3);   // 8*flux
    f.fy = make_float4(c0*gy0, c1*gy1, c2*gy2, c3*gy3);
    return f;
}

// out = base + (DT/64) * dsum8; u/v identity -> only 2 shuffles.
__device__ __forceinline__ float4 updrow(const float4 base,
                                         const Flux f0, const Flux f1,
                                         const Flux f2, const bool valid)
{
    const unsigned m = 0xffffffffu;
    const float p0 = f0.fx.x + 2.f*f1.fx.x + f2.fx.x;
    const float p1 = f0.fx.y + 2.f*f1.fx.y + f2.fx.y;
    const float p2 = f0.fx.z + 2.f*f1.fx.z + f2.fx.z;
    const float p3 = f0.fx.w + 2.f*f1.fx.w + f2.fx.w;
    const float q0 = f2.fy.x - f0.fy.x;
    const float q1 = f2.fy.y - f0.fy.y;
    const float q2 = f2.fy.z - f0.fy.z;
    const float q3 = f2.fy.w - f0.fy.w;

    const float u0 = p0 + q0, u1 = p1 + q1, u2 = p2 + q2, u3 = p3 + q3;
    const float v0 = q0 - p0, v1 = q1 - p1, v2 = q2 - p2, v3 = q3 - p3;

    const float vL = __shfl_up_sync(m, v3, 1);
    const float uR = __shfl_down_sync(m, u0, 1);

    const float d0 = fmaf(2.f, q0, vL) + u1;
    const float d1 = fmaf(2.f, q1, v0) + u2;
    const float d2 = fmaf(2.f, q2, v1) + u3;
    const float d3 = fmaf(2.f, q3, v2) + uR;

    float4 o;
    o.x = valid ? fmaf(DTC, d0, base.x) : 0.f;
    o.y = valid ? fmaf(DTC, d1, base.y) : 0.f;
    o.z = valid ? fmaf(DTC, d2, base.z) : 0.f;
    o.w = valid ? fmaf(DTC, d3, base.w) : 0.f;
    return o;
}

// Pipeline state + helpers. GUARD=true: boundary warps (per-lane column
// guard + row-range guard). GUARD=false: fully interior, no checks.
template<bool GUARD>
struct Pipe {
    const float* lp;       // next row to load
    int   ly;              // row index of lp (GUARD only)
    bool  colv;
    float4 i0, i1, i2, i3;
    Flux  f1a, f1b, f2a, f2b, f3a, f3b;
    float4 o1a, o1b, o2a, o2b;

    __device__ __forceinline__ float4 load() {
        float4 v;
        if (GUARD) {
            v = (colv && (unsigned)ly < (unsigned)H)
                    ? __ldg(reinterpret_cast<const float4*>(lp)) : mk4(0.f);
            ++ly;
        } else {
            v = __ldg(reinterpret_cast<const float4*>(lp));
        }
        lp += W;
        return v;
    }
    __device__ __forceinline__ bool rv(int y) const {
        return GUARD ? (colv && (unsigned)y < (unsigned)H) : true;
    }
};

// One pipeline step computing only the first S stages (S=6 = full step).
// Stage liveness during warm-up: o1 from k>=2, f2 from k>=4, o2 from k>=6,
// f3 from k>=8, o3 only in the main loop.
template<int S, bool GUARD>
__device__ __forceinline__ float4 do_step(Pipe<GUARD>& P, int y)
{
    const float4 inext = P.load();                  // 2 rows ahead of use
    const Flux f1c = fluxrow(P.i0, P.i1, P.i2, P.rv(y + 5));
    float4 o1c, o2c, o3 = mk4(0.f);
    Flux f2c, f3c;
    if constexpr (S >= 2) o1c = updrow(P.i0, P.f1a, P.f1b, f1c, P.rv(y + 4));
    if constexpr (S >= 3) f2c = fluxrow(P.o1a, P.o1b, o1c,      P.rv(y + 3));
    if constexpr (S >= 4) o2c = updrow(P.o1a, P.f2a, P.f2b, f2c, P.rv(y + 2));
    if constexpr (S >= 5) f3c = fluxrow(P.o2a, P.o2b, o2c,      P.rv(y + 1));
    if constexpr (S >= 6) o3  = updrow(P.o2a, P.f3a, P.f3b, f3c, P.rv(y));

    P.i0 = P.i1; P.i1 = P.i2; P.i2 = P.i3; P.i3 = inext;
    P.f1a = P.f1b; P.f1b = f1c;
    if constexpr (S >= 2) { P.o1a = P.o1b; P.o1b = o1c; }
    if constexpr (S >= 3) { P.f2a = P.f2b; P.f2b = f2c; }
    if constexpr (S >= 4) { P.o2a = P.o2b; P.o2b = o2c; }
    if constexpr (S >= 5) { P.f3a = P.f3b; P.f3b = f3c; }
    return o3;
}

template<bool GUARD>
__device__ __forceinline__ void run_strip(const float* __restrict__ img,
                                          float* __restrict__ op,
                                          const int x0, const int y0,
                                          const int nrows,
                                          const bool colv, const bool st_ok)
{
    Pipe<GUARD> P;
    P.lp = img + (size_t)(y0 - 6) * W + x0;
    P.ly = y0 - 6;
    P.colv = colv;

    float* sp = op + (size_t)y0 * W + x0;

    // 2-ahead load prefetch: i0..i2 window + i3 in flight
    P.i0 = P.load();
    P.i1 = P.load();
    P.i2 = P.load();
    P.i3 = P.load();

    Flux zf; zf.fx = mk4(0.f); zf.fy = mk4(0.f);
    P.f1a = zf; P.f1b = zf; P.f2a = zf; P.f2b = zf; P.f3a = zf; P.f3b = zf;
    P.o1a = mk4(0.f); P.o1b = P.o1a; P.o2a = P.o1a; P.o2b = P.o1a;

    // staged warm-up: compute only the live stages at each fill step
    (void)do_step<1>(P, y0 - 10);
    (void)do_step<1>(P, y0 - 9);
    (void)do_step<2>(P, y0 - 8);
    (void)do_step<2>(P, y0 - 7);
    (void)do_step<3>(P, y0 - 6);
    (void)do_step<3>(P, y0 - 5);
    (void)do_step<4>(P, y0 - 4);
    (void)do_step<4>(P, y0 - 3);
    (void)do_step<5>(P, y0 - 2);
    (void)do_step<5>(P, y0 - 1);

    if (GUARD) {
        #pragma unroll 2
        for (int y = y0; y < y0 + nrows; ++y) {
            const float4 o3 = do_step<6>(P, y);
            if (st_ok)
                *reinterpret_cast<float4*>(sp) = o3;
            sp += W;
        }
    } else {
        // interior: wide unroll so ptxas can overlap stages across steps
        #pragma unroll 4
        for (int y = y0; y < y0 + CHUNK; ++y) {
            const float4 o3 = do_step<6>(P, y);
            if (st_ok)
                *reinterpret_cast<float4*>(sp) = o3;
            sp += W;
        }
    }
}

__global__ __launch_bounds__(128, 4)       // cap 128 regs -> 4 blocks/SM
void pm_fused3(const float* __restrict__ in, float* __restrict__ out)
{
    const int lane = threadIdx.x & 31;
    const int warp = threadIdx.x >> 5;

    // flattened work item: 10 strips x 14 bands x 16 images = 2240 warps
    const int item  = blockIdx.x * 4 + warp;
    const int image = item / (NSTRIP * NBANDS);
    const int rem   = item - image * (NSTRIP * NBANDS);
    const int strip = rem / NBANDS;
    const int band  = rem - strip * NBANDS;

    const int x0 = strip * OUTWC - HALO + lane * 4;
    const int y0 = band * CHUNK;
    const int nrows = (band == NBANDS - 1) ? (H - y0) : CHUNK;   // 62 or 74

    const size_t plane = (size_t)image * (size_t)(H * W);
    const float* __restrict__ img = in  + plane;
    float*       __restrict__ op  = out + plane;

    const bool colv  = (x0 >= 0) && (x0 + 4 <= W);
    const bool st_ok = colv && (lane >= HALO / 4) && (lane < 32 - HALO / 4);

    const bool interior = (strip >= 1) && (strip <= NSTRIP - 2) &&
                          (band >= 1) && (y0 + CHUNK + 7 < H);

    if (interior)
        run_strip<false>(img, op, x0, y0, CHUNK, colv, st_ok);
    else
        run_strip<true>(img, op, x0, y0, nrows, colv, st_ok);
}

extern "C" void kernel_launch(void* const* d_in, const int* in_sizes, int n_in,
                              void* d_out, int out_size)
{
    const float* image = (const float*)d_in[0];
    float* out = (float*)d_out;

    // 2240 work items / 4 warps per block = 560 blocks: exactly one wave
    // at 4 blocks/SM residency (592 slots on 148 SMs).
    pm_fused3<<<560, 128>>>(image, out);
}